// round 8
// baseline (speedup 1.0000x reference)
#include <cuda_runtime.h>

#define N_IN  1024
#define N_OUT 512
#define BATCH 128
#define M     (N_IN + 1)    // 1025 word lines (weights + bias row)
#define TJ    8             // j-columns per block
#define NCH   16            // i-chunks -> grid 64*16 = 1024 blocks = one wave
#define NJT   (N_OUT / TJ)  // 64 j-tiles
#define NI_MAX 65           // max rows per chunk

// ---- device scratch (no allocations allowed) ----
__device__ unsigned g_maxbits;                   // bitwise max of |weights|; monotone, idempotent
__device__ float2   g_LS[M * BATCH];             // {lr, sign-bit-as-float} transposed [i][b]
__device__ float    g_A[NCH * BATCH * N_OUT];    // partials of s*(wp*pp - wn*qq)
__device__ float    g_B[NCH * BATCH * N_OUT];    // partials of s*(pp - qq)

__device__ __forceinline__ float ex2f_(float x) {
    float r; asm("ex2.approx.ftz.f32 %0, %1;" : "=f"(r) : "f"(x)); return r;
}
__device__ __forceinline__ float lg2f_(float x) {
    float r; asm("lg2.approx.ftz.f32 %0, %1;" : "=f"(r) : "f"(x)); return r;
}

// K0: LS transposed to [i][b] via 32x32 smem tiles.
//   l.x = 1 + log2|x|  (log2 of ratio = 2|x|;  -inf at x==0 -> ex2 -> +0)
//   l.y = sign bit of x as a float bit-pattern (0.0f / -0.0f); x==0 -> +0 bits.
// sign application in k_main is then a LOP3.XOR (ALU pipe), not an FMUL.
__global__ void __launch_bounds__(256) k_prep_ls(const float* __restrict__ x) {
    __shared__ float2 sm[32][33];
    const int tid = threadIdx.x;

    if (blockIdx.x < 128) {
        const int it = blockIdx.x >> 2;          // 0..31  (i-tile)
        const int bt = blockIdx.x & 3;           // 0..3   (b-tile)
        const int i0 = it * 32, b0 = bt * 32;
        const int tx = tid & 31, tz = tid >> 5;  // tz = 0..7

        #pragma unroll
        for (int r = 0; r < 4; ++r) {            // read coalesced over i
            int bl = tz + r * 8;
            float xv = x[(b0 + bl) * N_IN + i0 + tx];
            float lr = lg2f_(fabsf(xv)) + 1.0f;
            unsigned sb = __float_as_uint(xv) & 0x80000000u;
            sm[bl][tx] = make_float2(lr, __uint_as_float(sb));
        }
        __syncthreads();
        #pragma unroll
        for (int r = 0; r < 4; ++r) {            // write coalesced over b
            int il = tz + r * 8;
            g_LS[(i0 + il) * BATCH + b0 + tx] = sm[tx][il];
        }
    } else if (tid < BATCH) {                    // blockIdx.x == 128: bias line (x == 1)
        g_LS[N_IN * BATCH + tid] = make_float2(1.0f, 0.0f);
    }
}

// K1: main. Block = 128 threads (all b), TJ=8, NCH=16 (1024 blocks = one wave).
// Fill computes {wp, wn, Ep, En} and the block-local |w| max (each (i,j) visited
// exactly once grid-wide -> atomicMax builds the exact global max across the grid).
// Loop accumulates off-independent sums with the sign folded in by XOR:
//   spp = s*pp, sqq = s*qq  (XOR of sign bit, ALU pipe)
//   A += wp*spp - wn*sqq ;  B += spp - sqq
// k_reduce applies out = 0.5*(A + 0.25*maxw * B).
__global__ void __launch_bounds__(128) k_main(const float* __restrict__ wp,
                                              const float* __restrict__ wn,
                                              const float* __restrict__ bp,
                                              const float* __restrict__ bn,
                                              const float* __restrict__ noise) {
    __shared__ float4 sP[NI_MAX * TJ];           // 65*8*16B = 8.3 KB

    const int jt = blockIdx.x;                   // 0..63
    const int ch = blockIdx.y;                   // 0..15
    const int j0 = jt * TJ;
    const int i0 = (ch * M) / NCH;
    const int i1 = ((ch + 1) * M) / NCH;
    const int ni = i1 - i0;
    const int b  = threadIdx.x;

    float mx = 0.0f;
    for (int t = b; t < ni * TJ; t += 128) {
        int ii = t >> 3, jj = t & (TJ - 1);
        int i = i0 + ii, j = j0 + jj;
        float wpv = (i < N_IN) ? wp[i * N_OUT + j] : bp[j];
        float wnv = (i < N_IN) ? wn[i * N_OUT + j] : bn[j];
        mx = fmaxf(mx, fmaxf(fabsf(wpv), fabsf(wnv)));
        float2 z = reinterpret_cast<const float2*>(noise)[i * N_OUT + j]; // cols (2j,2j+1), row i
        float4 P;
        P.x =  wpv;
        P.y = -wnv;
        P.z = lg2f_(2.8f + 0.2f * z.x);
        P.w = lg2f_(2.8f + 0.2f * z.y);
        sP[t] = P;
    }
    #pragma unroll
    for (int o = 16; o; o >>= 1)
        mx = fmaxf(mx, __shfl_xor_sync(0xFFFFFFFFu, mx, o));
    if ((b & 31) == 0)
        atomicMax(&g_maxbits, __float_as_uint(mx));   // exact on non-negative floats
    __syncthreads();

    float accA[TJ], accB[TJ];
    #pragma unroll
    for (int jj = 0; jj < TJ; ++jj) { accA[jj] = 0.0f; accB[jj] = 0.0f; }

    const float2* __restrict__ ls = &g_LS[i0 * BATCH + b];
    float2 l = ls[0];
    #pragma unroll 2
    for (int ii = 0; ii < ni; ++ii) {
        int nxt = (ii + 1 < ni) ? (ii + 1) : ii;
        float2 lnext = ls[nxt * BATCH];           // branch-free prefetch
        unsigned sbit = __float_as_uint(l.y);
        #pragma unroll
        for (int jj = 0; jj < TJ; ++jj) {
            float4 p = sP[ii * TJ + jj];          // smem broadcast
            float pp = ex2f_(p.z * l.x);          // ratio^Ep  (>= 0)
            float qq = ex2f_(p.w * l.x);          // ratio^En
            float spp = __uint_as_float(__float_as_uint(pp) ^ sbit);  // s*pp (LOP3, ALU pipe)
            float sqq = __uint_as_float(__float_as_uint(qq) ^ sbit);  // s*qq
            accA[jj] = fmaf(p.x, spp, accA[jj]);
            accA[jj] = fmaf(p.y, sqq, accA[jj]);  // p.y = -wn
            accB[jj] += spp - sqq;
        }
        l = lnext;
    }

    const int base = (ch * BATCH + b) * N_OUT + j0;
    float4* dA = reinterpret_cast<float4*>(&g_A[base]);
    float4* dB = reinterpret_cast<float4*>(&g_B[base]);
    dA[0] = make_float4(accA[0], accA[1], accA[2], accA[3]);
    dA[1] = make_float4(accA[4], accA[5], accA[6], accA[7]);
    dB[0] = make_float4(accB[0], accB[1], accB[2], accB[3]);
    dB[1] = make_float4(accB[4], accB[5], accB[6], accB[7]);
}

// K2: deterministic fixed-order reduction (float2-vectorized), applies the offset last:
//   out = 0.5*(sum_A + 0.25*maxw * sum_B)
__global__ void __launch_bounds__(256) k_reduce(float* __restrict__ out) {
    int t = blockIdx.x * blockDim.x + threadIdx.x;   // one float2 (two outputs) per thread
    if (t >= (BATCH * N_OUT) / 2) return;
    const float off = 0.25f * __uint_as_float(g_maxbits);
    const float2* a2 = reinterpret_cast<const float2*>(g_A);
    const float2* b2 = reinterpret_cast<const float2*>(g_B);
    float2 sa = make_float2(0.f, 0.f), sb = make_float2(0.f, 0.f);
    #pragma unroll
    for (int ch = 0; ch < NCH; ++ch) {
        float2 va = a2[ch * (BATCH * N_OUT / 2) + t];
        float2 vb = b2[ch * (BATCH * N_OUT / 2) + t];
        sa.x += va.x; sa.y += va.y;
        sb.x += vb.x; sb.y += vb.y;
    }
    float2 r;
    r.x = 0.5f * fmaf(off, sb.x, sa.x);
    r.y = 0.5f * fmaf(off, sb.y, sa.y);
    reinterpret_cast<float2*>(out)[t] = r;
}

extern "C" void kernel_launch(void* const* d_in, const int* in_sizes, int n_in,
                              void* d_out, int out_size) {
    const float* x     = (const float*)d_in[0];   // (128, 1024)
    const float* w_pos = (const float*)d_in[1];   // (1024, 512)
    const float* w_neg = (const float*)d_in[2];   // (1024, 512)
    const float* b_pos = (const float*)d_in[3];   // (512,)
    const float* b_neg = (const float*)d_in[4];   // (512,)
    const float* noise = (const float*)d_in[5];   // (1025, 1024)
    float* out = (float*)d_out;                   // (128, 512)

    k_prep_ls<<<129, 256>>>(x);
    dim3 grid(NJT, NCH);
    k_main<<<grid, 128>>>(w_pos, w_neg, b_pos, b_neg, noise);
    k_reduce<<<(BATCH * N_OUT / 2 + 255) / 256, 256>>>(out);
}